// round 3
// baseline (speedup 1.0000x reference)
#include <cuda_runtime.h>

#define NN 8192
#define DD 64
#define EK 262144
#define EHK 262144
#define TAB 8192
#define CAP 256

// Scratch (device globals: allocation-free)
__device__ float g_sk[NN * DD];      // normalized state_K
__device__ float g_g[NN];            // tanh(state_H)
__device__ float g_fHa[NN];          // f_H edge accumulator
__device__ int   g_cnt[NN];          // per-row payload counts
__device__ int2  g_list[NN * CAP];   // (src_row, coef_bits) payloads (16MB)
__device__ float g_tab[TAB + 1];     // dE(s) lookup table, s in [-1,1]

__device__ __forceinline__ float warp_sum(float v) {
    #pragma unroll
    for (int o = 16; o; o >>= 1) v += __shfl_xor_sync(0xFFFFFFFFu, v, o);
    return v;
}

// --- prep: normalize sk rows, g=tanh(sH), zero cnt/fHa, build dE table.
__global__ void prep_kernel(const float* __restrict__ sH, const float* __restrict__ sK,
                            const float* __restrict__ w1, const float* __restrict__ b1,
                            const float* __restrict__ w2) {
    int warp = threadIdx.x >> 5, lane = threadIdx.x & 31;
    int row = blockIdx.x * 8 + warp;
    float2 v = ((const float2*)(sK + row * DD))[lane];
    float ss = warp_sum(v.x * v.x + v.y * v.y);
    float inv = rsqrtf(ss);
    ((float2*)(g_sk + row * DD))[lane] = make_float2(v.x * inv, v.y * inv);
    if (lane == 0) g_g[row] = tanhf(sH[row]);

    int gt = blockIdx.x * 256 + threadIdx.x;
    if (gt < NN) { g_cnt[gt] = 0; g_fHa[gt] = 0.f; }
    if (gt <= TAB) {
        float s = gt * (2.0f / TAB) - 1.0f;
        float acc = 0.f;
        #pragma unroll 8
        for (int h = 0; h < 64; h++)
            acc += tanhf(s * __ldg(w1 + h) + __ldg(b1 + h)) * __ldg(w2 + h);
        g_tab[gt] = acc;
    }
}

// matvec body: f_H[row] = -sH[row] + W_H[row,:] @ g  (+ fHa if requested)
__device__ __forceinline__ void matvec_row(int row, const float* __restrict__ sH,
                                           const float* __restrict__ W,
                                           float* __restrict__ out, bool addFHa,
                                           float* rr) {
    int lane = threadIdx.x & 31, warp = threadIdx.x >> 5;
    const float4* Wr = (const float4*)(W + (size_t)row * NN);
    const float4* g4 = (const float4*)g_g;
    float acc = 0.f;
    #pragma unroll
    for (int it = 0; it < 8; it++) {
        int k = threadIdx.x + it * 256;
        float4 w = __ldcs(Wr + k);
        float4 g = g4[k];
        acc += w.x * g.x + w.y * g.y + w.z * g.z + w.w * g.w;
    }
    acc = warp_sum(acc);
    if (lane == 0) rr[warp] = acc;
    __syncthreads();
    if (threadIdx.x == 0) {
        float v = rr[0] + rr[1] + rr[2] + rr[3] + rr[4] + rr[5] + rr[6] + rr[7];
        out[row] = -sH[row] + v + (addFHa ? g_fHa[row] : 0.f);
    }
}

// --- phase 2: edge pass (dot + coef -> payload lists) interleaved with matvec rows 0..4095.
//     grid = 17*4096 = 69632 blocks; b%17==0 -> matvec, else edge block (8 warps).
__global__ __launch_bounds__(256) void edge_kernel(
    const float* __restrict__ sH, const float* __restrict__ W,
    const int* __restrict__ indK, const int* __restrict__ indHK,
    float* __restrict__ out)
{
    __shared__ float rr[8];
    int b = blockIdx.x;
    int m = b / 17;
    if (b - m * 17 == 0) { matvec_row(m, sH, W, out, false, rr); return; }

    int eb = b - m - 1;                 // 0..65535
    int lane = threadIdx.x & 31, warp = threadIdx.x >> 5;
    float coef;
    int i, j;
    if (eb < EHK / 8) {
        int e = eb * 8 + warp;
        int2 ij = __ldg((const int2*)indHK + e);
        i = ij.x; j = ij.y;
        float2 a = ((const float2*)(g_sk + i * DD))[lane];
        float2 bb = ((const float2*)(g_sk + j * DD))[lane];
        float gram = warp_sum(a.x * bb.x + a.y * bb.y);
        float gi = __ldg(g_g + i), gj = __ldg(g_g + j);
        if (lane == 0)  atomicAdd(g_fHa + i, gram * gj * 0.5f);   // /KAPPA_H
        if (lane == 16) atomicAdd(g_fHa + j, gram * gi * 0.5f);
        coef = -0.5f * gi * gj;                                   // -G/KAPPA_K
    } else {
        int e = (eb - EHK / 8) * 8 + warp;
        int2 pq = __ldg((const int2*)indK + e);
        i = pq.x; j = pq.y;
        float2 a = ((const float2*)(g_sk + i * DD))[lane];
        float2 bb = ((const float2*)(g_sk + j * DD))[lane];
        float s = warp_sum(a.x * bb.x + a.y * bb.y);
        float t = (fminf(fmaxf(s, -1.f), 1.f) + 1.f) * (TAB * 0.5f);
        int i0 = min((int)t, TAB - 1);
        float f = t - (float)i0;
        float t0 = __ldg(g_tab + i0), t1 = __ldg(g_tab + i0 + 1);
        coef = t0 + (t1 - t0) * f;                                // dE(s)
    }
    if (lane == 0 || lane == 16) {
        int dst = (lane == 0) ? i : j;
        int src = (lane == 0) ? j : i;
        int slot = atomicAdd(g_cnt + dst, 1);
        g_list[dst * CAP + slot] = make_int2(src, __float_as_int(coef));
    }
}

// --- phase 3: gather + finalize (warp-per-row) interleaved with matvec rows 4096..8191.
//     grid = 5*1024 = 5120; b%5==0 -> gather block (8 rows), else matvec.
__global__ __launch_bounds__(256) void gather_kernel(
    const float* __restrict__ sH, const float* __restrict__ W,
    const float* __restrict__ omega, float* __restrict__ out)
{
    __shared__ float rr[8];
    int b = blockIdx.x;
    int gblk = b / 5;
    if (b - gblk * 5 != 0) {
        int id = b - gblk - 1;          // 0..4095
        matvec_row(4096 + id, sH, W, out, true, rr);
        return;
    }

    __shared__ float A[DD * DD];
    __shared__ float srow[8 * DD];
    for (int k = threadIdx.x; k < DD * DD; k += 256) {
        int rI = k >> 6, c = k & 63;
        A[k] = 0.5f * (__ldg(omega + k) - __ldg(omega + c * DD + rI));
    }
    __syncthreads();

    int warp = threadIdx.x >> 5, lane = threadIdx.x & 31;
    int row = gblk * 8 + warp;
    int deg = g_cnt[row];
    const int2* lst = g_list + row * CAP;

    float ax = 0.f, ay = 0.f;
    int base = 0;
    for (; base + 32 <= deg; base += 32) {
        #pragma unroll
        for (int k = 0; k < 32; k++) {
            int2 ee = __ldg(lst + base + k);           // broadcast (L1 hot)
            float c = __int_as_float(ee.y);
            float2 v = ((const float2*)(g_sk + ee.x * DD))[lane];
            ax += c * v.x; ay += c * v.y;
        }
    }
    for (int k = base; k < deg; k++) {
        int2 ee = __ldg(lst + k);
        float c = __int_as_float(ee.y);
        float2 v = ((const float2*)(g_sk + ee.x * DD))[lane];
        ax += c * v.x; ay += c * v.y;
    }

    // finalize: f_K = -acc + sk*<sk,acc> + sk @ (omega-omega^T)/2
    float2 skv = ((const float2*)(g_sk + row * DD))[lane];
    float d = warp_sum(skv.x * ax + skv.y * ay);
    ((float2*)(srow + warp * DD))[lane] = skv;
    __syncwarp();
    const float* sr = srow + warp * DD;
    const float2* A2 = (const float2*)A;
    float m0 = 0.f, m1 = 0.f;
    #pragma unroll
    for (int k = 0; k < DD; k++) {
        float sv = sr[k];
        float2 av = A2[k * 32 + lane];
        m0 += sv * av.x;
        m1 += sv * av.y;
    }
    float o0 = -ax + skv.x * d + m0;
    float o1 = -ay + skv.y * d + m1;
    ((float2*)(out + NN + row * DD))[lane] = make_float2(o0, o1);
    if (lane == 0 && row < 4096) out[row] += g_fHa[row];   // finish K2-phase f_H rows
}

extern "C" void kernel_launch(void* const* d_in, const int* in_sizes, int n_in,
                              void* d_out, int out_size) {
    const float* sH   = (const float*)d_in[0];
    const float* sK   = (const float*)d_in[1];
    const float* WH   = (const float*)d_in[2];
    const float* om   = (const float*)d_in[3];
    const float* w1   = (const float*)d_in[4];
    const float* b1   = (const float*)d_in[5];
    const float* w2   = (const float*)d_in[6];
    const int*  indK  = (const int*)d_in[7];
    const int*  indHK = (const int*)d_in[8];
    float* out = (float*)d_out;

    prep_kernel<<<NN / 8, 256>>>(sH, sK, w1, b1, w2);
    edge_kernel<<<17 * 4096, 256>>>(sH, WH, indK, indHK, out);
    gather_kernel<<<5 * 1024, 256>>>(sH, WH, om, out);
}

// round 4
// speedup vs baseline: 1.3851x; 1.3851x over previous
#include <cuda_runtime.h>

#define NN 8192
#define DD 64
#define EK 262144
#define EHK 262144
#define TAB 8192

// Scratch (device globals: allocation-free)
__device__ float g_sk[NN * DD];   // normalized state_K
__device__ float g_g[NN];         // tanh(state_H)
__device__ float g_fK[NN * DD];   // f_K edge accumulator
__device__ float g_fHa[NN];       // f_H edge accumulator (decoupled from matvec)
__device__ float g_tab[TAB + 1];  // dE(s) lookup table, s in [-1,1]

__device__ __forceinline__ void red4(float* p, float a, float b, float c, float d) {
    asm volatile("red.global.add.v4.f32 [%0], {%1,%2,%3,%4};"
                 :: "l"(p), "f"(a), "f"(b), "f"(c), "f"(d) : "memory");
}

__device__ __forceinline__ float warp_sum(float v) {
    #pragma unroll
    for (int o = 16; o; o >>= 1) v += __shfl_xor_sync(0xFFFFFFFFu, v, o);
    return v;
}

// --- prep: normalize state_K rows (warp-per-row, 8/block), g=tanh(sH),
//     zero accumulators, build dE(s) table. 1024 blocks x 256 threads.
__global__ void prep_kernel(const float* __restrict__ sH, const float* __restrict__ sK,
                            const float* __restrict__ w1, const float* __restrict__ b1,
                            const float* __restrict__ w2) {
    int warp = threadIdx.x >> 5, lane = threadIdx.x & 31;
    int row = blockIdx.x * 8 + warp;
    float2 v = ((const float2*)(sK + row * DD))[lane];
    float ss = warp_sum(v.x * v.x + v.y * v.y);
    float inv = rsqrtf(ss);
    ((float2*)(g_sk + row * DD))[lane] = make_float2(v.x * inv, v.y * inv);
    if (lane == 0) g_g[row] = tanhf(sH[row]);

    int gt = blockIdx.x * 256 + threadIdx.x;          // 0..262143
    if (gt < NN * DD / 4) ((float4*)g_fK)[gt] = make_float4(0.f, 0.f, 0.f, 0.f);
    if (gt < NN / 4)      ((float4*)g_fHa)[gt] = make_float4(0.f, 0.f, 0.f, 0.f);
    if (gt <= TAB) {
        float s = gt * (2.0f / TAB) - 1.0f;
        float acc = 0.f;
        #pragma unroll 8
        for (int h = 0; h < 64; h++)
            acc += tanhf(s * __ldg(w1 + h) + __ldg(b1 + h)) * __ldg(w2 + h);
        g_tab[gt] = acc;
    }
}

// --- mega kernel: matvec rows, HK edges and K edges interleaved 1:4:4.
//     73728 blocks of 256 threads; all three workloads independent.
__global__ __launch_bounds__(256, 6) void mega_kernel(
    const float* __restrict__ sH, const float* __restrict__ W,
    const int* __restrict__ indK, const int* __restrict__ indHK,
    float* __restrict__ out)
{
    __shared__ float rr[8];
    int grp = blockIdx.x / 9;
    int r   = blockIdx.x - grp * 9;
    int lane = threadIdx.x & 31, warp = threadIdx.x >> 5;

    if (r == 0) {
        // ---- matvec: f_H[grp] = -sH[grp] + W_H[grp,:] @ g  (streaming loads)
        const float4* Wr = (const float4*)(W + (size_t)grp * NN);
        const float4* g4 = (const float4*)g_g;
        float acc = 0.f;
        #pragma unroll
        for (int it = 0; it < 8; it++) {
            int k = threadIdx.x + it * 256;
            float4 w = __ldcs(Wr + k);     // stream: don't pollute L2
            float4 g = g4[k];
            acc += w.x * g.x + w.y * g.y + w.z * g.z + w.w * g.w;
        }
        acc = warp_sum(acc);
        if (lane == 0) rr[warp] = acc;
        __syncthreads();
        if (threadIdx.x == 0) {
            float v = rr[0] + rr[1] + rr[2] + rr[3] + rr[4] + rr[5] + rr[6] + rr[7];
            out[grp] = -sH[grp] + v;
        }
    } else if (r <= 4) {
        // ---- HK edge: warp-per-edge
        int e = (grp * 4 + (r - 1)) * 8 + warp;
        int2 ij = __ldg((const int2*)indHK + e);
        int i = ij.x, j = ij.y;
        float2 a = ((const float2*)(g_sk + i * DD))[lane];
        float2 b = ((const float2*)(g_sk + j * DD))[lane];
        float gram = warp_sum(a.x * b.x + a.y * b.y);
        float gi = __ldg(g_g + i), gj = __ldg(g_g + j);
        if (lane == 0)  atomicAdd(g_fHa + i, gram * gj * 0.5f);   // /KAPPA_H
        if (lane == 16) atomicAdd(g_fHa + j, gram * gi * 0.5f);
        float coef = -0.5f * gi * gj;                 // -G/KAPPA_K
        int half = lane >> 4, l4 = lane & 15;
        int dstRow = half ? j : i;
        int srcRow = half ? i : j;
        float4 s = ((const float4*)(g_sk + srcRow * DD))[l4];
        red4(g_fK + dstRow * DD + l4 * 4, coef * s.x, coef * s.y, coef * s.z, coef * s.w);
    } else {
        // ---- K edge: warp-per-edge, dE via table lookup (replaces 64x tanhf)
        int e = (grp * 4 + (r - 5)) * 8 + warp;
        int2 pq = __ldg((const int2*)indK + e);
        int p = pq.x, q = pq.y;
        float2 a = ((const float2*)(g_sk + p * DD))[lane];
        float2 b = ((const float2*)(g_sk + q * DD))[lane];
        float s = warp_sum(a.x * b.x + a.y * b.y);
        float t = (fminf(fmaxf(s, -1.f), 1.f) + 1.f) * (TAB * 0.5f);
        int i0 = min((int)t, TAB - 1);
        float f = t - (float)i0;
        float t0 = __ldg(g_tab + i0), t1 = __ldg(g_tab + i0 + 1);
        float dE = t0 + (t1 - t0) * f;                // dE(s)
        int half = lane >> 4, l4 = lane & 15;
        int dstRow = half ? q : p;
        int srcRow = half ? p : q;
        float4 v = ((const float4*)(g_sk + srcRow * DD))[l4];
        red4(g_fK + dstRow * DD + l4 * 4, dE * v.x, dE * v.y, dE * v.z, dE * v.w);
    }
}

// --- finalize: f_H += fHacc; f_K = -acc + sk*<sk,acc> + sk @ (omega-omega^T)/2.
__global__ void fin_kernel(const float* __restrict__ omega, float* __restrict__ out) {
    __shared__ float A[DD * DD];      // antisymmetrized omega
    __shared__ float srow[8 * DD];
    for (int k = threadIdx.x; k < DD * DD; k += 256) {
        int rI = k >> 6, c = k & 63;
        A[k] = 0.5f * (omega[k] - omega[c * DD + rI]);
    }
    __syncthreads();
    int warp = threadIdx.x >> 5, lane = threadIdx.x & 31;
    int row = blockIdx.x * 8 + warp;
    if (lane == 0) out[row] += g_fHa[row];            // finish f_H
    float2 skv = ((const float2*)(g_sk + row * DD))[lane];
    float2 fv  = ((const float2*)(g_fK + row * DD))[lane];
    float d = warp_sum(skv.x * fv.x + skv.y * fv.y);
    ((float2*)(srow + warp * DD))[lane] = skv;
    __syncwarp();
    const float* sr = srow + warp * DD;
    const float2* A2 = (const float2*)A;
    float m0 = 0.f, m1 = 0.f;
    #pragma unroll
    for (int k = 0; k < DD; k++) {
        float sv = sr[k];
        float2 av = A2[k * 32 + lane];
        m0 += sv * av.x;
        m1 += sv * av.y;
    }
    float o0 = -fv.x + skv.x * d + m0;
    float o1 = -fv.y + skv.y * d + m1;
    ((float2*)(out + NN + row * DD))[lane] = make_float2(o0, o1);
}

extern "C" void kernel_launch(void* const* d_in, const int* in_sizes, int n_in,
                              void* d_out, int out_size) {
    const float* sH   = (const float*)d_in[0];
    const float* sK   = (const float*)d_in[1];
    const float* WH   = (const float*)d_in[2];
    const float* om   = (const float*)d_in[3];
    const float* w1   = (const float*)d_in[4];
    const float* b1   = (const float*)d_in[5];
    const float* w2   = (const float*)d_in[6];
    const int*  indK  = (const int*)d_in[7];
    const int*  indHK = (const int*)d_in[8];
    float* out = (float*)d_out;

    prep_kernel<<<NN / 8, 256>>>(sH, sK, w1, b1, w2);
    mega_kernel<<<9 * NN, 256>>>(sH, WH, indK, indHK, out);
    fin_kernel<<<NN / 8, 256>>>(om, out);
}

// round 5
// speedup vs baseline: 1.5455x; 1.1158x over previous
#include <cuda_runtime.h>

#define NN 8192
#define DD 64
#define EK 262144
#define EHK 262144
#define TAB 2048
#define MB 296                 // matvec worker blocks (2 per SM)
#define EB 592                 // edge worker blocks (4 per SM)
#define EWARPS (EB * 8)        // 4736 edge warps

// Scratch (device globals: allocation-free)
__device__ float g_sk[NN * DD];   // normalized state_K
__device__ float g_g[NN];         // tanh(state_H)
__device__ float g_fK[NN * DD];   // f_K edge accumulator
__device__ float g_fHa[NN];       // f_H edge accumulator
__device__ float g_tab[TAB + 1];  // dE(s) lookup table, s in [-1,1]

__device__ __forceinline__ void red4(float* p, float a, float b, float c, float d) {
    asm volatile("red.global.add.v4.f32 [%0], {%1,%2,%3,%4};"
                 :: "l"(p), "f"(a), "f"(b), "f"(c), "f"(d) : "memory");
}

__device__ __forceinline__ float warp_sum(float v) {
    #pragma unroll
    for (int o = 16; o; o >>= 1) v += __shfl_xor_sync(0xFFFFFFFFu, v, o);
    return v;
}

// --- prep: normalize state_K rows, g=tanh(sH), zero accumulators, build table.
__global__ void prep_kernel(const float* __restrict__ sH, const float* __restrict__ sK,
                            const float* __restrict__ w1, const float* __restrict__ b1,
                            const float* __restrict__ w2) {
    int warp = threadIdx.x >> 5, lane = threadIdx.x & 31;
    int row = blockIdx.x * 8 + warp;
    float2 v = ((const float2*)(sK + row * DD))[lane];
    float ss = warp_sum(v.x * v.x + v.y * v.y);
    float inv = rsqrtf(ss);
    ((float2*)(g_sk + row * DD))[lane] = make_float2(v.x * inv, v.y * inv);
    if (lane == 0) g_g[row] = tanhf(sH[row]);

    int gt = blockIdx.x * 256 + threadIdx.x;          // 0..262143
    if (gt < NN * DD / 4) ((float4*)g_fK)[gt] = make_float4(0.f, 0.f, 0.f, 0.f);
    if (gt < NN / 4)      ((float4*)g_fHa)[gt] = make_float4(0.f, 0.f, 0.f, 0.f);
    if (gt <= TAB) {
        float s = gt * (2.0f / TAB) - 1.0f;
        float acc = 0.f;
        #pragma unroll 8
        for (int h = 0; h < 64; h++)
            acc += tanhf(s * __ldg(w1 + h) + __ldg(b1 + h)) * __ldg(w2 + h);
        g_tab[gt] = acc;
    }
}

// --- mega: persistent workers. Blocks 0..MB-1: matvec rows (grid-stride).
//     Blocks MB..MB+EB-1: edges (warp grid-stride over EHK+EK jobs).
__global__ __launch_bounds__(256, 6) void mega_kernel(
    const float* __restrict__ sH, const float* __restrict__ W,
    const int* __restrict__ indK, const int* __restrict__ indHK,
    float* __restrict__ out)
{
    int lane = threadIdx.x & 31, warp = threadIdx.x >> 5;

    if (blockIdx.x < MB) {
        // ---- matvec worker: rows blockIdx.x, +MB, ... keeps DRAM saturated.
        __shared__ float rr[8];
        const float4* g4 = (const float4*)g_g;
        for (int row = blockIdx.x; row < NN; row += MB) {
            const float4* Wr = (const float4*)(W + (size_t)row * NN);
            float acc = 0.f;
            #pragma unroll
            for (int it = 0; it < 8; it++) {
                int k = threadIdx.x + it * 256;
                float4 w = __ldcs(Wr + k);     // stream: don't pollute L2
                float4 g = g4[k];
                acc += w.x * g.x + w.y * g.y + w.z * g.z + w.w * g.w;
            }
            acc = warp_sum(acc);
            if (lane == 0) rr[warp] = acc;
            __syncthreads();
            if (threadIdx.x == 0) {
                float v = rr[0] + rr[1] + rr[2] + rr[3] + rr[4] + rr[5] + rr[6] + rr[7];
                out[row] = -sH[row] + v;
            }
            __syncthreads();
        }
        return;
    }

    // ---- edge worker: warp-per-edge, half-warp per endpoint.
    int c = lane & 15;                    // float4 chunk within row
    int wg = (blockIdx.x - MB) * 8 + warp;
    #pragma unroll 2
    for (int e = wg; e < EHK + EK; e += EWARPS) {
        bool isHK = e < EHK;
        int2 ij = isHK ? __ldg((const int2*)indHK + e)
                       : __ldg((const int2*)indK + (e - EHK));
        int myRow = (lane < 16) ? ij.x : ij.y;
        float4 v = __ldg((const float4*)(g_sk + myRow * DD) + c);
        float4 w;                          // partner row chunk
        w.x = __shfl_xor_sync(0xFFFFFFFFu, v.x, 16);
        w.y = __shfl_xor_sync(0xFFFFFFFFu, v.y, 16);
        w.z = __shfl_xor_sync(0xFFFFFFFFu, v.z, 16);
        w.w = __shfl_xor_sync(0xFFFFFFFFu, v.w, 16);
        float d = v.x * w.x + v.y * w.y + v.z * w.z + v.w * w.w;
        d += __shfl_xor_sync(0xFFFFFFFFu, d, 1);
        d += __shfl_xor_sync(0xFFFFFFFFu, d, 2);
        d += __shfl_xor_sync(0xFFFFFFFFu, d, 4);
        d += __shfl_xor_sync(0xFFFFFFFFu, d, 8);   // s = <row_i, row_j>
        float coef;
        if (isHK) {
            float gm = __ldg(g_g + myRow);
            float gp = __shfl_xor_sync(0xFFFFFFFFu, gm, 16);
            if (lane == 0)  atomicAdd(g_fHa + ij.x, d * gp * 0.5f);  // /KAPPA_H
            if (lane == 16) atomicAdd(g_fHa + ij.y, d * gp * 0.5f);
            coef = -0.5f * gm * gp;                                  // -G/KAPPA_K
        } else {
            float t = (fminf(fmaxf(d, -1.f), 1.f) + 1.f) * (TAB * 0.5f);
            int i0 = min((int)t, TAB - 1);
            float f = t - (float)i0;
            float t0 = __ldg(g_tab + i0), t1 = __ldg(g_tab + i0 + 1);
            coef = t0 + (t1 - t0) * f;                               // dE(s)
        }
        // endpoint myRow accumulates coef * partner_row (chunks already in w)
        red4(g_fK + myRow * DD + c * 4, coef * w.x, coef * w.y, coef * w.z, coef * w.w);
    }
}

// --- finalize: f_H += fHacc; f_K = -acc + sk*<sk,acc> + sk @ (omega-omega^T)/2.
__global__ void fin_kernel(const float* __restrict__ omega, float* __restrict__ out) {
    __shared__ float A[DD * DD];      // antisymmetrized omega
    __shared__ float srow[8 * DD];
    for (int k = threadIdx.x; k < DD * DD; k += 256) {
        int rI = k >> 6, cc = k & 63;
        A[k] = 0.5f * (omega[k] - omega[cc * DD + rI]);
    }
    __syncthreads();
    int warp = threadIdx.x >> 5, lane = threadIdx.x & 31;
    int row = blockIdx.x * 8 + warp;
    if (lane == 0) out[row] += g_fHa[row];            // finish f_H
    float2 skv = ((const float2*)(g_sk + row * DD))[lane];
    float2 fv  = ((const float2*)(g_fK + row * DD))[lane];
    float d = warp_sum(skv.x * fv.x + skv.y * fv.y);
    ((float2*)(srow + warp * DD))[lane] = skv;
    __syncwarp();
    const float* sr = srow + warp * DD;
    const float2* A2 = (const float2*)A;
    float m0 = 0.f, m1 = 0.f;
    #pragma unroll
    for (int k = 0; k < DD; k++) {
        float sv = sr[k];
        float2 av = A2[k * 32 + lane];
        m0 += sv * av.x;
        m1 += sv * av.y;
    }
    float o0 = -fv.x + skv.x * d + m0;
    float o1 = -fv.y + skv.y * d + m1;
    ((float2*)(out + NN + row * DD))[lane] = make_float2(o0, o1);
}

extern "C" void kernel_launch(void* const* d_in, const int* in_sizes, int n_in,
                              void* d_out, int out_size) {
    const float* sH   = (const float*)d_in[0];
    const float* sK   = (const float*)d_in[1];
    const float* WH   = (const float*)d_in[2];
    const float* om   = (const float*)d_in[3];
    const float* w1   = (const float*)d_in[4];
    const float* b1   = (const float*)d_in[5];
    const float* w2   = (const float*)d_in[6];
    const int*  indK  = (const int*)d_in[7];
    const int*  indHK = (const int*)d_in[8];
    float* out = (float*)d_out;

    prep_kernel<<<NN / 8, 256>>>(sH, sK, w1, b1, w2);
    mega_kernel<<<MB + EB, 256>>>(sH, WH, indK, indHK, out);
    fin_kernel<<<NN / 8, 256>>>(om, out);
}